// round 2
// baseline (speedup 1.0000x reference)
#include <cuda_runtime.h>
#include <cstdint>

// Problem constants (fixed by the dataset)
#define MAXN 50000
#define MAXE 600000

// ---------------- scratch (static device allocations; no cudaMalloc) ----------------
__device__ __align__(16) float g_deg[MAXN];        // degree, then dinv = rsqrt(deg)
__device__ int   g_src[MAXE];
__device__ int   g_dst[MAXE];
__device__ __align__(16) float g_agg[MAXN * 128];  // aggregated 128-ch buffer
__device__ __align__(16) float g_h1 [MAXN * 256];  // layer-1 hidden (256 ch)
__device__ __align__(16) float g_t  [MAXN * 128];  // transform output (128 ch)
__device__ __align__(16) float g_t3 [MAXN * 2];    // layer-3 transform
__device__ __align__(16) float g_a3 [MAXN * 2];    // layer-3 aggregate
__device__ int g_is32;                             // 1 if edge_index arrived as int32

// ---------------- edge dtype probe ----------------
__global__ void k_flag_init() { g_is32 = 0; }

// int64 nonneg small values => every odd 32-bit word is 0.
// int32 edge data => odd words are edge IDs, essentially never all zero.
__global__ void k_probe(const unsigned* __restrict__ w, int nPairs) {
    int i = blockIdx.x * blockDim.x + threadIdx.x;
    if (i < nPairs && w[2 * i + 1] != 0u) g_is32 = 1;
}

// ---------------- graph prep ----------------
__global__ void k_init_deg(int n) {
    int i = blockIdx.x * blockDim.x + threadIdx.x;
    if (i < n) g_deg[i] = 1.0f;                      // self-loop
}

__global__ void k_prep_edges(const void* __restrict__ ei, int E, int N) {
    int e = blockIdx.x * blockDim.x + threadIdx.x;
    if (e >= E) return;
    int s, d;
    if (g_is32) {
        const int* p = (const int*)ei;
        s = p[e]; d = p[E + e];
    } else {
        const long long* p = (const long long*)ei;
        s = (int)p[e]; d = (int)p[E + e];
    }
    // defensive clamp: wrong guess degrades to rel_err failure, not a fault
    s = min(max(s, 0), N - 1);
    d = min(max(d, 0), N - 1);
    g_src[e] = s;
    g_dst[e] = d;
    atomicAdd(&g_deg[d], 1.0f);
}

__global__ void k_finish_deg(int n) {
    int i = blockIdx.x * blockDim.x + threadIdx.x;
    if (i < n) g_deg[i] = rsqrtf(g_deg[i]);          // deg > 0 always (self-loop)
}

// ---------------- aggregation (C = 128) ----------------
// self-loop init: agg[i] = dinv[i]^2 * h[i]   (also serves as the zero-init)
__global__ void k_self_init128(const float* __restrict__ h, float* __restrict__ agg, int total4) {
    int idx = blockIdx.x * blockDim.x + threadIdx.x;   // over N*32 float4s
    if (idx >= total4) return;
    int node = idx >> 5;
    float di = g_deg[node];
    float nm = di * di;
    float4 v = ((const float4*)h)[idx];
    v.x *= nm; v.y *= nm; v.z *= nm; v.w *= nm;
    ((float4*)agg)[idx] = v;
}

// one warp per edge; each lane handles 4 channels; vector L2 red
__global__ void k_scatter128(const float* __restrict__ h, float* __restrict__ agg, int E) {
    int e = blockIdx.x * (blockDim.x >> 5) + (threadIdx.x >> 5);
    if (e >= E) return;
    int lane = threadIdx.x & 31;
    int s = g_src[e];
    int d = g_dst[e];
    float nm = g_deg[s] * g_deg[d];
    float4 v = ((const float4*)(h + (size_t)s * 128))[lane];
    v.x *= nm; v.y *= nm; v.z *= nm; v.w *= nm;
    float* p = agg + (size_t)d * 128 + lane * 4;
    asm volatile("red.global.add.v4.f32 [%0], {%1,%2,%3,%4};"
                 :: "l"(p), "f"(v.x), "f"(v.y), "f"(v.z), "f"(v.w) : "memory");
}

// bias + relu, in place (C = 128)
__global__ void k_bias_relu128(float* __restrict__ h, const float* __restrict__ b, int total4) {
    int idx = blockIdx.x * blockDim.x + threadIdx.x;
    if (idx >= total4) return;
    int c4 = idx & 31;
    float4 v  = ((float4*)h)[idx];
    float4 bb = ((const float4*)b)[c4];
    v.x = fmaxf(v.x + bb.x, 0.f);
    v.y = fmaxf(v.y + bb.y, 0.f);
    v.z = fmaxf(v.z + bb.z, 0.f);
    v.w = fmaxf(v.w + bb.w, 0.f);
    ((float4*)h)[idx] = v;
}

// ---------------- SGEMM 128x128 tile, 8x8 per thread ----------------
template<bool RELU, bool BIAS>
__global__ __launch_bounds__(256) void k_sgemm(
    int M, int N, int K,
    const float* __restrict__ A, const float* __restrict__ B,
    const float* __restrict__ bias, float* __restrict__ C)
{
    __shared__ float As[8][128];
    __shared__ float Bs[8][128];
    const int tid = threadIdx.x;
    const int br = blockIdx.y, bc = blockIdx.x;
    const int rowA = tid >> 1;             // 0..127
    const int colA = (tid & 1) << 2;       // 0 or 4
    const int rowB = tid >> 5;             // 0..7
    const int colB = (tid & 31) << 2;      // 0..124
    const int tr = (tid >> 4) << 3;
    const int tc = (tid & 15) << 3;
    float acc[8][8] = {};
    const int aRow = br * 128 + rowA;
    const bool aValid = aRow < M;
    const float* Ag = A + (size_t)aRow * K + colA;
    const float* Bg = B + (size_t)rowB * N + bc * 128 + colB;

    for (int k0 = 0; k0 < K; k0 += 8) {
        float4 av = aValid ? *(const float4*)(Ag + k0) : make_float4(0.f, 0.f, 0.f, 0.f);
        float4 bv = *(const float4*)(Bg + (size_t)k0 * N);
        As[colA + 0][rowA] = av.x;
        As[colA + 1][rowA] = av.y;
        As[colA + 2][rowA] = av.z;
        As[colA + 3][rowA] = av.w;
        *(float4*)&Bs[rowB][colB] = bv;
        __syncthreads();
#pragma unroll
        for (int k = 0; k < 8; ++k) {
            float ra[8], rb[8];
#pragma unroll
            for (int i = 0; i < 8; i++) ra[i] = As[k][tr + i];
#pragma unroll
            for (int j = 0; j < 8; j++) rb[j] = Bs[k][tc + j];
#pragma unroll
            for (int i = 0; i < 8; i++)
#pragma unroll
                for (int j = 0; j < 8; j++) acc[i][j] += ra[i] * rb[j];
        }
        __syncthreads();
    }

#pragma unroll
    for (int i = 0; i < 8; i++) {
        int r = br * 128 + tr + i;
        if (r >= M) break;
#pragma unroll
        for (int j = 0; j < 8; j += 4) {
            int c = bc * 128 + tc + j;
            float4 v = make_float4(acc[i][j], acc[i][j + 1], acc[i][j + 2], acc[i][j + 3]);
            if (BIAS) {
                v.x += bias[c]; v.y += bias[c + 1]; v.z += bias[c + 2]; v.w += bias[c + 3];
            }
            if (RELU) {
                v.x = fmaxf(v.x, 0.f); v.y = fmaxf(v.y, 0.f);
                v.z = fmaxf(v.z, 0.f); v.w = fmaxf(v.w, 0.f);
            }
            *(float4*)&C[(size_t)r * N + c] = v;
        }
    }
}

// ---------------- layer-3 GEMM (128 -> 2), warp per node, fused self-loop init ----------------
__global__ void k_gemm3(const float* __restrict__ h, const float* __restrict__ W3, int M) {
    int node = blockIdx.x * (blockDim.x >> 5) + (threadIdx.x >> 5);
    if (node >= M) return;
    int lane = threadIdx.x & 31;
    float4 v = ((const float4*)(h + (size_t)node * 128))[lane];
    int k = lane * 4;
    float a0 = v.x * W3[2 * k + 0] + v.y * W3[2 * k + 2] + v.z * W3[2 * k + 4] + v.w * W3[2 * k + 6];
    float a1 = v.x * W3[2 * k + 1] + v.y * W3[2 * k + 3] + v.z * W3[2 * k + 5] + v.w * W3[2 * k + 7];
#pragma unroll
    for (int o = 16; o; o >>= 1) {
        a0 += __shfl_xor_sync(0xffffffffu, a0, o);
        a1 += __shfl_xor_sync(0xffffffffu, a1, o);
    }
    if (lane == 0) {
        g_t3[node * 2 + 0] = a0;
        g_t3[node * 2 + 1] = a1;
        float di = g_deg[node];
        float nm = di * di;
        g_a3[node * 2 + 0] = nm * a0;
        g_a3[node * 2 + 1] = nm * a1;
    }
}

__global__ void k_scatter2(int E) {
    int e = blockIdx.x * blockDim.x + threadIdx.x;
    if (e >= E) return;
    int s = g_src[e];
    int d = g_dst[e];
    float nm = g_deg[s] * g_deg[d];
    atomicAdd(&g_a3[d * 2 + 0], nm * g_t3[s * 2 + 0]);
    atomicAdd(&g_a3[d * 2 + 1], nm * g_t3[s * 2 + 1]);
}

__global__ void k_logsoftmax(const float* __restrict__ b3, float* __restrict__ out, int M) {
    int i = blockIdx.x * blockDim.x + threadIdx.x;
    if (i >= M) return;
    float a = g_a3[2 * i + 0] + b3[0];
    float b = g_a3[2 * i + 1] + b3[1];
    float m = fmaxf(a, b);
    float l = m + logf(expf(a - m) + expf(b - m));
    out[2 * i + 0] = a - l;
    out[2 * i + 1] = b - l;
}

// ---------------- orchestration ----------------
extern "C" void kernel_launch(void* const* d_in, const int* in_sizes, int n_in,
                              void* d_out, int out_size)
{
    const float* x  = (const float*)d_in[0];
    const float* W1 = (const float*)d_in[1];
    const float* b1 = (const float*)d_in[2];
    const float* W2 = (const float*)d_in[3];
    const float* b2 = (const float*)d_in[4];
    const float* W3 = (const float*)d_in[5];
    const float* b3 = (const float*)d_in[6];
    const void*  ei = (const void*)d_in[7];
    float* out = (float*)d_out;

    const int IN   = 128;
    const int H1   = in_sizes[2];            // 256
    const int H2   = in_sizes[4];            // 128
    const int N    = in_sizes[0] / IN;       // 50000
    const int E    = in_sizes[7] / 2;        // 600000
    (void)n_in; (void)out_size; (void)H2;

    float *p_agg, *p_h1, *p_t;
    cudaGetSymbolAddress((void**)&p_agg, g_agg);
    cudaGetSymbolAddress((void**)&p_h1,  g_h1);
    cudaGetSymbolAddress((void**)&p_t,   g_t);

    const int T = 256;
    const int nodeBlocks  = (N + T - 1) / T;
    const int edgeBlocks  = (E + T - 1) / T;
    const int n4          = N * 32;                    // N*128/4 float4s
    const int vecBlocks   = (n4 + T - 1) / T;
    const int warpBlocksE = (E + 7) / 8;               // 8 warps/block
    const int warpBlocksN = (N + 7) / 8;

    // edge dtype probe: pairs of 32-bit words spanning min(int32, int64) footprint
    const int nPairs = E;                              // E pairs cover E int64s or 2E int32s
    k_flag_init<<<1, 1>>>();
    k_probe<<<(nPairs + T - 1) / T, T>>>((const unsigned*)ei, nPairs);

    // graph normalization
    k_init_deg<<<nodeBlocks, T>>>(N);
    k_prep_edges<<<edgeBlocks, T>>>(ei, E, N);
    k_finish_deg<<<nodeBlocks, T>>>(N);

    // ---- layer 1: aggregate-first:  h1 = relu( (A x) W1 + b1 ) ----
    k_self_init128<<<vecBlocks, T>>>(x, p_agg, n4);
    k_scatter128<<<warpBlocksE, T>>>(x, p_agg, E);
    {
        dim3 grid(H1 / 128, (N + 127) / 128);
        k_sgemm<true, true><<<grid, 256>>>(N, H1, IN, p_agg, W1, b1, p_h1);
    }

    // ---- layer 2: transform-first:  h2 = relu( A (h1 W2) + b2 ) ----
    {
        dim3 grid(1, (N + 127) / 128);                 // H2 = 128
        k_sgemm<false, false><<<grid, 256>>>(N, 128, H1, p_h1, W2, nullptr, p_t);
    }
    k_self_init128<<<vecBlocks, T>>>(p_t, p_agg, n4);
    k_scatter128<<<warpBlocksE, T>>>(p_t, p_agg, E);
    k_bias_relu128<<<vecBlocks, T>>>(p_agg, b2, n4);

    // ---- layer 3: transform-first:  out = log_softmax( A (h2 W3) + b3 ) ----
    k_gemm3<<<warpBlocksN, T>>>(p_agg, W3, N);
    k_scatter2<<<edgeBlocks, T>>>(E);
    k_logsoftmax<<<nodeBlocks, T>>>(b3, out, N);
}

// round 4
// speedup vs baseline: 1.0954x; 1.0954x over previous
#include <cuda_runtime.h>
#include <cstdint>

#define MAXN 50000
#define MAXE 600000

// ---------------- scratch ----------------
__device__ __align__(16) float g_deg[MAXN];
__device__ int   g_src[MAXE];
__device__ int   g_dst[MAXE];
__device__ __align__(16) float g_agg[MAXN * 128];
__device__ __align__(16) float g_h1 [MAXN * 256];
__device__ __align__(16) float g_t  [MAXN * 128];
__device__ __align__(16) float g_t3 [MAXN * 2];
__device__ __align__(16) float g_a3 [MAXN * 2];
__device__ int g_is32;

// ---------------- graph prep ----------------
__global__ void k_init_deg(int n) {
    int i = blockIdx.x * blockDim.x + threadIdx.x;
    if (i == 0) g_is32 = 0;
    if (i < n) g_deg[i] = 1.0f;
}

__global__ void k_probe(const unsigned* __restrict__ w, int nPairs) {
    int i = blockIdx.x * blockDim.x + threadIdx.x;
    if (i < nPairs && w[2 * i + 1] != 0u) g_is32 = 1;
}

__global__ void k_prep_edges(const void* __restrict__ ei, int E, int N) {
    int e = blockIdx.x * blockDim.x + threadIdx.x;
    if (e >= E) return;
    int s, d;
    if (g_is32) {
        const int* p = (const int*)ei;
        s = p[e]; d = p[E + e];
    } else {
        const long long* p = (const long long*)ei;
        s = (int)p[e]; d = (int)p[E + e];
    }
    s = min(max(s, 0), N - 1);
    d = min(max(d, 0), N - 1);
    g_src[e] = s;
    g_dst[e] = d;
    atomicAdd(&g_deg[d], 1.0f);
}

__global__ void k_finish_deg(int n) {
    int i = blockIdx.x * blockDim.x + threadIdx.x;
    if (i < n) g_deg[i] = rsqrtf(g_deg[i]);
}

// ---------------- aggregation (C = 128) ----------------
__global__ void k_self_init128(const float* __restrict__ h, float* __restrict__ agg, int total4) {
    int idx = blockIdx.x * blockDim.x + threadIdx.x;
    if (idx >= total4) return;
    int node = idx >> 5;
    float di = g_deg[node];
    float nm = di * di;
    float4 v = ((const float4*)h)[idx];
    v.x *= nm; v.y *= nm; v.z *= nm; v.w *= nm;
    ((float4*)agg)[idx] = v;
}

__global__ void k_scatter128(const float* __restrict__ h, float* __restrict__ agg, int E) {
    int e = blockIdx.x * (blockDim.x >> 5) + (threadIdx.x >> 5);
    if (e >= E) return;
    int lane = threadIdx.x & 31;
    int s = g_src[e];
    int d = g_dst[e];
    float nm = g_deg[s] * g_deg[d];
    float4 v = ((const float4*)(h + (size_t)s * 128))[lane];
    v.x *= nm; v.y *= nm; v.z *= nm; v.w *= nm;
    float* p = agg + (size_t)d * 128 + lane * 4;
    asm volatile("red.global.add.v4.f32 [%0], {%1,%2,%3,%4};"
                 :: "l"(p), "f"(v.x), "f"(v.y), "f"(v.z), "f"(v.w) : "memory");
}

// ---------------- SGEMM with packed fma.rn.f32x2 ----------------
// C[M, Ntot] = A[M, K] @ W[K, Ntot], 128x128 tile, 8x8 per thread (accs as 32 f32x2).
// MODE 0: C = relu(out + bias)            (layer 1 -> h1)
// MODE 1: C = out; g_agg = deg^2 * out    (layer 2 -> t, fused self-loop init)
template<int MODE>
__global__ __launch_bounds__(256) void k_sgemm_f2(
    int M, int Ntot, int K,
    const float* __restrict__ A, const float* __restrict__ B,
    const float* __restrict__ bias, float* __restrict__ C)
{
    __shared__ float As[8][128];
    __shared__ float Bs[8][128];
    const int tid = threadIdx.x;
    const int br = blockIdx.y, bc = blockIdx.x;
    const int rowA = tid >> 1;
    const int colA = (tid & 1) << 2;
    const int rowB = tid >> 5;
    const int colB = (tid & 31) << 2;
    const int tr = (tid >> 4) << 3;
    const int tc = (tid & 15) << 3;

    unsigned long long acc[8][4];
#pragma unroll
    for (int i = 0; i < 8; i++)
#pragma unroll
        for (int j = 0; j < 4; j++) acc[i][j] = 0ull;

    const int aRow = br * 128 + rowA;
    const bool aValid = aRow < M;
    const float* Ag = A + (size_t)aRow * K + colA;
    const float* Bg = B + (size_t)rowB * Ntot + bc * 128 + colB;

    for (int k0 = 0; k0 < K; k0 += 8) {
        float4 av = aValid ? *(const float4*)(Ag + k0) : make_float4(0.f, 0.f, 0.f, 0.f);
        float4 bv = *(const float4*)(Bg + (size_t)k0 * Ntot);
        As[colA + 0][rowA] = av.x;
        As[colA + 1][rowA] = av.y;
        As[colA + 2][rowA] = av.z;
        As[colA + 3][rowA] = av.w;
        *(float4*)&Bs[rowB][colB] = bv;
        __syncthreads();
#pragma unroll
        for (int k = 0; k < 8; ++k) {
            unsigned long long b2[4];
#pragma unroll
            for (int j = 0; j < 4; j++)
                b2[j] = *(const unsigned long long*)&Bs[k][tc + j * 2];
#pragma unroll
            for (int i = 0; i < 8; i++) {
                float ra = As[k][tr + i];
                unsigned long long a2;
                asm("mov.b64 %0, {%1, %1};" : "=l"(a2) : "f"(ra));
#pragma unroll
                for (int j = 0; j < 4; j++)
                    asm("fma.rn.f32x2 %0, %1, %2, %3;"
                        : "=l"(acc[i][j]) : "l"(a2), "l"(b2[j]), "l"(acc[i][j]));
            }
        }
        __syncthreads();
    }

#pragma unroll
    for (int i = 0; i < 8; i++) {
        int r = br * 128 + tr + i;
        if (r >= M) break;
        float nm = 0.f;
        if (MODE == 1) { float di = g_deg[r]; nm = di * di; }
#pragma unroll
        for (int jj = 0; jj < 2; jj++) {
            int c = bc * 128 + tc + jj * 4;
            float4 v;
            asm("mov.b64 {%0, %1}, %2;" : "=f"(v.x), "=f"(v.y) : "l"(acc[i][jj * 2 + 0]));
            asm("mov.b64 {%0, %1}, %2;" : "=f"(v.z), "=f"(v.w) : "l"(acc[i][jj * 2 + 1]));
            if (MODE == 0) {
                const float4 bb = *(const float4*)(bias + c);
                v.x = fmaxf(v.x + bb.x, 0.f);
                v.y = fmaxf(v.y + bb.y, 0.f);
                v.z = fmaxf(v.z + bb.z, 0.f);
                v.w = fmaxf(v.w + bb.w, 0.f);
                *(float4*)&C[(size_t)r * Ntot + c] = v;
            } else {
                *(float4*)&C[(size_t)r * Ntot + c] = v;
                float4 a = make_float4(nm * v.x, nm * v.y, nm * v.z, nm * v.w);
                *(float4*)&g_agg[(size_t)r * 128 + (tc + jj * 4)] = a;
            }
        }
    }
}

// ---------------- layer-3: fused bias2+relu, 128 -> 2, self-loop init ----------------
__global__ void k_gemm3(const float* __restrict__ agg, const float* __restrict__ b2,
                        const float* __restrict__ W3, int M) {
    int node = blockIdx.x * (blockDim.x >> 5) + (threadIdx.x >> 5);
    if (node >= M) return;
    int lane = threadIdx.x & 31;
    float4 v  = ((const float4*)(agg + (size_t)node * 128))[lane];
    float4 bb = ((const float4*)b2)[lane];
    v.x = fmaxf(v.x + bb.x, 0.f);
    v.y = fmaxf(v.y + bb.y, 0.f);
    v.z = fmaxf(v.z + bb.z, 0.f);
    v.w = fmaxf(v.w + bb.w, 0.f);
    int k = lane * 4;
    float a0 = v.x * W3[2 * k + 0] + v.y * W3[2 * k + 2] + v.z * W3[2 * k + 4] + v.w * W3[2 * k + 6];
    float a1 = v.x * W3[2 * k + 1] + v.y * W3[2 * k + 3] + v.z * W3[2 * k + 5] + v.w * W3[2 * k + 7];
#pragma unroll
    for (int o = 16; o; o >>= 1) {
        a0 += __shfl_xor_sync(0xffffffffu, a0, o);
        a1 += __shfl_xor_sync(0xffffffffu, a1, o);
    }
    if (lane == 0) {
        g_t3[node * 2 + 0] = a0;
        g_t3[node * 2 + 1] = a1;
        float di = g_deg[node];
        float nm = di * di;
        g_a3[node * 2 + 0] = nm * a0;
        g_a3[node * 2 + 1] = nm * a1;
    }
}

__global__ void k_scatter2(int E) {
    int e = blockIdx.x * blockDim.x + threadIdx.x;
    if (e >= E) return;
    int s = g_src[e];
    int d = g_dst[e];
    float nm = g_deg[s] * g_deg[d];
    atomicAdd(&g_a3[d * 2 + 0], nm * g_t3[s * 2 + 0]);
    atomicAdd(&g_a3[d * 2 + 1], nm * g_t3[s * 2 + 1]);
}

__global__ void k_logsoftmax(const float* __restrict__ b3, float* __restrict__ out, int M) {
    int i = blockIdx.x * blockDim.x + threadIdx.x;
    if (i >= M) return;
    float a = g_a3[2 * i + 0] + b3[0];
    float b = g_a3[2 * i + 1] + b3[1];
    float m = fmaxf(a, b);
    float l = m + logf(expf(a - m) + expf(b - m));
    out[2 * i + 0] = a - l;
    out[2 * i + 1] = b - l;
}

// ---------------- orchestration ----------------
extern "C" void kernel_launch(void* const* d_in, const int* in_sizes, int n_in,
                              void* d_out, int out_size)
{
    const float* x  = (const float*)d_in[0];
    const float* W1 = (const float*)d_in[1];
    const float* b1 = (const float*)d_in[2];
    const float* W2 = (const float*)d_in[3];
    const float* b2 = (const float*)d_in[4];
    const float* W3 = (const float*)d_in[5];
    const float* b3 = (const float*)d_in[6];
    const void*  ei = (const void*)d_in[7];
    float* out = (float*)d_out;

    const int IN = 128;
    const int H1 = in_sizes[2];            // 256
    const int N  = in_sizes[0] / IN;       // 50000
    const int E  = in_sizes[7] / 2;        // 600000
    (void)n_in; (void)out_size;

    float *p_agg, *p_h1, *p_t;
    cudaGetSymbolAddress((void**)&p_agg, g_agg);
    cudaGetSymbolAddress((void**)&p_h1,  g_h1);
    cudaGetSymbolAddress((void**)&p_t,   g_t);

    const int T = 256;
    const int nodeBlocks  = (N + T - 1) / T;
    const int edgeBlocks  = (E + T - 1) / T;
    const int n4          = N * 32;
    const int vecBlocks   = (n4 + T - 1) / T;
    const int warpBlocksE = (E + 7) / 8;
    const int warpBlocksN = (N + 7) / 8;
    const int mTiles      = (N + 127) / 128;

    // graph normalization (+ edge dtype probe)
    k_init_deg<<<nodeBlocks, T>>>(N);
    k_probe<<<(E + T - 1) / T, T>>>((const unsigned*)ei, E);
    k_prep_edges<<<edgeBlocks, T>>>(ei, E, N);
    k_finish_deg<<<nodeBlocks, T>>>(N);

    // ---- layer 1: aggregate-first:  h1 = relu( (A x) W1 + b1 ) ----
    k_self_init128<<<vecBlocks, T>>>(x, p_agg, n4);
    k_scatter128<<<warpBlocksE, T>>>(x, p_agg, E);
    {
        dim3 grid(H1 / 128, mTiles);
        k_sgemm_f2<0><<<grid, 256>>>(N, H1, IN, p_agg, W1, b1, p_h1);
    }

    // ---- layer 2: transform-first:  t = h1 W2 ; agg = selfinit(t) fused ----
    {
        dim3 grid(1, mTiles);
        k_sgemm_f2<1><<<grid, 256>>>(N, 128, H1, p_h1, W2, nullptr, p_t);
    }
    k_scatter128<<<warpBlocksE, T>>>(p_t, p_agg, E);

    // ---- layer 3: h2 = relu(agg + b2) fused; out = log_softmax( A (h2 W3) + b3 ) ----
    k_gemm3<<<warpBlocksN, T>>>(p_agg, b2, W3, N);
    k_scatter2<<<edgeBlocks, T>>>(E);
    k_logsoftmax<<<nodeBlocks, T>>>(b3, out, N);
}